// round 14
// baseline (speedup 1.0000x reference)
#include <cuda_runtime.h>
#include <cuda_fp16.h>
#include <cstdint>
#include <cstddef>
#include <cstring>

#define NM 16384
#define ND 2048
#define NE 64
#define TM 256
#define KC 64
#define NSPLIT 2
#define KQ (ND/NSPLIT)      // 1024 k per CTA
#define NSTG (KQ/KC)        // 16 stages
#define NMT (NM/TM)         // 64 m-tiles

#define XROWB 288           // x row stride bytes (72 floats) -> conflict-free LDS.64
#define XBUF_SZ (TM*XROWB)  // 73728 per stage
#define WOFF (2*XBUF_SZ)    // 147456
#define WSTG 16384          // W hi(8K)+lo(8K) per stage
#define SMEM_BYTES (WOFF + 2*WSTG)  // 180224

#define SW128(o) ((o) ^ (((o) >> 3) & 0x70))

__device__ __align__(16) __half g_Whi[NE * ND];
__device__ __align__(16) __half g_Wlo[NE * ND];
__device__ __align__(16) float  g_part[NSPLIT][NM][NE];   // 8 MB split-K partials
__device__ unsigned g_flag[NMT];

// ---------- helpers ----------
__device__ __forceinline__ uint32_t smem_u32(const void* p) {
    uint32_t a;
    asm("{ .reg .u64 t; cvta.to.shared.u64 t, %1; cvt.u32.u64 %0, t; }" : "=r"(a) : "l"(p));
    return a;
}
__device__ __forceinline__ void cpa16(uint32_t dst, const void* src) {
    uint64_t g = __cvta_generic_to_global((void*)src);
    asm volatile("cp.async.cg.shared.global [%0], [%1], 16;" :: "r"(dst), "l"(g) : "memory");
}
__device__ __forceinline__ void cpa_commit() {
    asm volatile("cp.async.commit_group;" ::: "memory");
}
__device__ __forceinline__ void cpa_wait1() {
    asm volatile("cp.async.wait_group 1;" ::: "memory");
}
__device__ __forceinline__ void ldm4(uint32_t* r, uint32_t addr) {
    asm volatile("ldmatrix.sync.aligned.m8n8.x4.shared.b16 {%0,%1,%2,%3}, [%4];"
                 : "=r"(r[0]), "=r"(r[1]), "=r"(r[2]), "=r"(r[3]) : "r"(addr));
}
__device__ __forceinline__ void mma16816(float* d, const uint32_t* a, uint32_t b0, uint32_t b1) {
    asm volatile(
        "mma.sync.aligned.m16n8k16.row.col.f32.f16.f16.f32 "
        "{%0,%1,%2,%3}, {%4,%5,%6,%7}, {%8,%9}, {%0,%1,%2,%3};"
        : "+f"(d[0]), "+f"(d[1]), "+f"(d[2]), "+f"(d[3])
        : "r"(a[0]), "r"(a[1]), "r"(a[2]), "r"(a[3]), "r"(b0), "r"(b1));
}
__device__ __forceinline__ void split2(float2 v, uint32_t& hi, uint32_t& lo) {
    __half2 h = __floats2half2_rn(v.x, v.y);
    float2 hf = __half22float2(h);
    __half2 l = __floats2half2_rn(v.x - hf.x, v.y - hf.y);
    memcpy(&hi, &h, 4); memcpy(&lo, &l, 4);
}

// ---------- W prep (grid 128): coalesced transpose-split; also zero flags ----------
__global__ __launch_bounds__(256)
void prep_W(const float* __restrict__ W) {
    if (blockIdx.x == 0 && threadIdx.x < NMT) g_flag[threadIdx.x] = 0;
    __shared__ float t[16][65];
    const int tid = threadIdx.x;
    const int kb = blockIdx.x * 16;
    {
        const int r = tid >> 4, c4 = (tid & 15) * 4;
        float4 v = *(const float4*)&W[(size_t)(kb + r) * NE + c4];
        t[r][c4] = v.x; t[r][c4 + 1] = v.y; t[r][c4 + 2] = v.z; t[r][c4 + 3] = v.w;
    }
    __syncthreads();
    const int e = tid >> 2, kc = tid & 3;
    __half hi[4], lo[4];
    #pragma unroll
    for (int j = 0; j < 4; j++) {
        const float v = t[kc * 4 + j][e];
        const __half h = __float2half_rn(v);
        hi[j] = h;
        lo[j] = __float2half_rn(v - __half2float(h));
    }
    uint2 uh, ul;
    memcpy(&uh, hi, 8); memcpy(&ul, lo, 8);
    const size_t off = (size_t)e * ND + kb + kc * 4;
    *(uint2*)&g_Whi[off] = uh;
    *(uint2*)&g_Wlo[off] = ul;
}

// ---------- GEMM (R7 structure) + fused split-K epilogue ----------
__global__ __launch_bounds__(256, 1)
void router_mma(const float* __restrict__ x, const float* __restrict__ bias,
                const float* __restrict__ noise, float* __restrict__ out)
{
    extern __shared__ __align__(1024) char smem[];
    const uint32_t sb = smem_u32(smem);

    const int tid = threadIdx.x, wid = tid >> 5, lane = tid & 31;
    const int gid = lane >> 2, t = lane & 3;
    const int m0 = blockIdx.x * TM;
    const int z  = blockIdx.y;
    const int kbase = z * KQ;

    const int q = lane >> 3, lr = lane & 7;
    const uint32_t b_base = (uint32_t)((((q >> 1) * 8) + lr) * 128 + (q & 1) * 16);

    float acc[16][4];
    #pragma unroll
    for (int i = 0; i < 16; i++)
        #pragma unroll
        for (int j = 0; j < 4; j++) acc[i][j] = 0.0f;

    const int we = tid >> 2, wj = tid & 3;   // unused pattern kept minimal below

    auto issue = [&](int s) {
        if (s < NSTG) {
            const uint32_t xb = sb + (s & 1) * XBUF_SZ;
            const int k0 = kbase + s * KC;
            #pragma unroll
            for (int i = 0; i < 16; i++) {
                const int id = tid + 256 * i;
                const int row = id >> 4, c = id & 15;
                cpa16(xb + row * XROWB + c * 16,
                      &x[(size_t)(m0 + row) * ND + k0 + c * 4]);
            }
            const uint32_t wb = sb + WOFF + (s & 1) * WSTG;
            #pragma unroll
            for (int i = 0; i < 2; i++) {
                const int id = tid + 256 * i;
                const int e = id >> 3, j = id & 7;
                const uint32_t so = SW128((uint32_t)(e * 128 + j * 16));
                cpa16(wb + so,        &g_Whi[(size_t)e * ND + k0 + j * 8]);
                cpa16(wb + 8192 + so, &g_Wlo[(size_t)e * ND + k0 + j * 8]);
            }
        }
        cpa_commit();
    };

    issue(0);
    for (int s = 0; s < NSTG; s++) {
        issue(s + 1);
        cpa_wait1();
        __syncthreads();

        const char* xp = smem + (s & 1) * XBUF_SZ;
        const uint32_t wh = sb + WOFF + (s & 1) * WSTG, wlo = wh + 8192;

        #pragma unroll
        for (int kc = 0; kc < 2; kc++) {
            // load all B fragments for this kc pair (kc covers k32: two k16 halves)
            #pragma unroll
            for (int kh = 0; kh < 2; kh++) {
                const int kk = kc * 2 + kh;
                uint32_t ah[2][4], al[2][4];
                #pragma unroll
                for (int sub = 0; sub < 2; sub++) {
                    const int row = wid * 32 + sub * 16 + gid;
                    const char* rp = xp + row * XROWB + (kk * 16 + 2 * t) * 4;
                    float2 a0 = *(const float2*)(rp);
                    float2 a1 = *(const float2*)(rp + 8 * XROWB);
                    float2 a2 = *(const float2*)(rp + 32);
                    float2 a3 = *(const float2*)(rp + 8 * XROWB + 32);
                    split2(a0, ah[sub][0], al[sub][0]);
                    split2(a1, ah[sub][1], al[sub][1]);
                    split2(a2, ah[sub][2], al[sub][2]);
                    split2(a3, ah[sub][3], al[sub][3]);
                }
                const uint32_t bo = SW128(b_base + kk * 32);
                #pragma unroll
                for (int nb = 0; nb < 4; nb++) {
                    uint32_t bh[4], bl[4];
                    ldm4(bh, wh  + bo + nb * 2048);
                    ldm4(bl, wlo + bo + nb * 2048);
                    #pragma unroll
                    for (int sub = 0; sub < 2; sub++) {
                        float* p0 = acc[sub * 8 + 2 * nb];
                        float* p1 = acc[sub * 8 + 2 * nb + 1];
                        mma16816(p0, ah[sub], bh[0], bh[1]);
                        mma16816(p0, ah[sub], bl[0], bl[1]);
                        mma16816(p0, al[sub], bh[0], bh[1]);
                        mma16816(p1, ah[sub], bh[2], bh[3]);
                        mma16816(p1, ah[sub], bl[2], bl[3]);
                        mma16816(p1, al[sub], bh[2], bh[3]);
                    }
                }
            }
        }
        __syncthreads();
    }

    // ---- write fp32 partials ----
    #pragma unroll
    for (int sub = 0; sub < 2; sub++) {
        const int token = m0 + wid * 32 + sub * 16 + gid;
        #pragma unroll
        for (int nf = 0; nf < 8; nf++) {
            const int e0 = nf * 8 + 2 * t;
            float* p = &g_part[z][token][e0];
            *(float2*)p            = make_float2(acc[sub * 8 + nf][0], acc[sub * 8 + nf][1]);
            *(float2*)(p + 8 * NE) = make_float2(acc[sub * 8 + nf][2], acc[sub * 8 + nf][3]);
        }
    }

    // ---- split-K fused epilogue: second arriver does softmax + top-2 ----
    __threadfence();
    __syncthreads();
    __shared__ unsigned s_last;
    if (tid == 0) s_last = atomicAdd(&g_flag[blockIdx.x], 1u);
    __syncthreads();
    if (s_last == 0) return;                 // first arriver exits
    if (tid == 0) g_flag[blockIdx.x] = 0;    // reset for next graph replay
    __threadfence();

    {
        const int token = m0 + tid;          // 256 threads, 1 token each
        float v[NE];
        float mx = -3.0e38f;
        #pragma unroll
        for (int j = 0; j < NE / 4; j++) {
            float4 a  = *(const float4*)&g_part[0][token][4 * j];
            float4 b  = *(const float4*)&g_part[1][token][4 * j];
            float4 nz = *(const float4*)&noise[(size_t)token * NE + 4 * j];
            float4 bb = *(const float4*)&bias[4 * j];
            v[4*j+0] = a.x + b.x + bb.x + 0.1f * nz.x;
            v[4*j+1] = a.y + b.y + bb.y + 0.1f * nz.y;
            v[4*j+2] = a.z + b.z + bb.z + 0.1f * nz.z;
            v[4*j+3] = a.w + b.w + bb.w + 0.1f * nz.w;
            mx = fmaxf(mx, fmaxf(fmaxf(v[4*j], v[4*j+1]), fmaxf(v[4*j+2], v[4*j+3])));
        }
        float sum = 0.0f;
        #pragma unroll
        for (int e = 0; e < NE; e++) { v[e] = expf(v[e] - mx); sum += v[e]; }
        const float inv = 1.0f / sum;

        float m1 = -1.0f, m2 = -1.0f;
        int i1 = 0, i2 = 0;
        float* out_sc = out + (size_t)NM * 4;
        #pragma unroll
        for (int j = 0; j < NE / 4; j++) {
            float4 o;
            o.x = v[4*j+0] * inv; o.y = v[4*j+1] * inv;
            o.z = v[4*j+2] * inv; o.w = v[4*j+3] * inv;
            *(float4*)&out_sc[(size_t)token * NE + 4 * j] = o;
            float vs[4] = {o.x, o.y, o.z, o.w};
            #pragma unroll
            for (int l = 0; l < 4; l++) {
                const int idx = 4 * j + l;
                const float val = vs[l];
                if (val > m1)      { m2 = m1; i2 = i1; m1 = val; i1 = idx; }
                else if (val > m2) { m2 = val; i2 = idx; }
            }
        }
        out[(size_t)token * 2 + 0] = m1;
        out[(size_t)token * 2 + 1] = m2;
        out[(size_t)NM * 2 + (size_t)token * 2 + 0] = (float)i1;
        out[(size_t)NM * 2 + (size_t)token * 2 + 1] = (float)i2;
    }
}

extern "C" void kernel_launch(void* const* d_in, const int* in_sizes, int n_in,
                              void* d_out, int out_size) {
    const float* x     = (const float*)d_in[0];
    const float* W     = (const float*)d_in[1];
    const float* b     = (const float*)d_in[2];
    const float* noise = (const float*)d_in[3];

    cudaFuncSetAttribute(router_mma, cudaFuncAttributeMaxDynamicSharedMemorySize, SMEM_BYTES);

    prep_W<<<ND / 16, 256>>>(W);
    router_mma<<<dim3(NM / TM, NSPLIT, 1), 256, SMEM_BYTES>>>(x, b, noise, (float*)d_out);
}